// round 14
// baseline (speedup 1.0000x reference)
#include <cuda_runtime.h>
#include <cuda_bf16.h>

#define NMAX 100000
#define EMAX 1600000
#define NBKT 512   // 64 degree buckets x 8 salt

// Scratch (allocation-free rule: device globals)
__device__ __nv_bfloat16 g_bufT[NMAX * 64];  // bf16 messages (t0, L0)
__device__ __nv_bfloat16 g_bufA[NMAX * 64];  // bf16 messages (h0*so, L1)
__device__ __nv_bfloat16 g_bufC[NMAX * 16];  // t2 (16-feat messages, bf16)
__device__ float g_so[NMAX];                 // rsqrt(max(deg_out,1))
__device__ float g_si[NMAX];                 // rsqrt(max(deg_in,1))
__device__ int   g_deg[2 * NMAX + 1];        // [0,N): degO  [N,2N): degI  [2N]: base allocator
__device__ int   g_rank[EMAX];               // edge rank within dst segment
__device__ int   g_rowptr[NMAX];             // ABSOLUTE CSR segment starts
__device__ int   g_csrc[EMAX];               // CSR: src ids grouped by dst
__device__ int   g_hist[NBKT];               // degree-bucket histogram
__device__ int   g_hbase[NBKT];              // bucket bases (then cursors)
__device__ int   g_perm[NMAX];               // degree-sorted node order

static inline int cdiv(int a, int b) { return (a + b - 1) / b; }

// ---- bf16 pack/unpack helpers ----
__device__ __forceinline__ float4 bf4_to_f4(uint2 r) {
    __nv_bfloat162 lo = *reinterpret_cast<__nv_bfloat162*>(&r.x);
    __nv_bfloat162 hi = *reinterpret_cast<__nv_bfloat162*>(&r.y);
    float2 a = __bfloat1622float2(lo), b = __bfloat1622float2(hi);
    return make_float4(a.x, a.y, b.x, b.y);
}
__device__ __forceinline__ uint2 f4_to_bf4(float4 v) {
    __nv_bfloat162 lo = __float22bfloat162_rn(make_float2(v.x, v.y));
    __nv_bfloat162 hi = __float22bfloat162_rn(make_float2(v.z, v.w));
    uint2 r;
    r.x = *reinterpret_cast<unsigned*>(&lo);
    r.y = *reinterpret_cast<unsigned*>(&hi);
    return r;
}
__device__ __forceinline__ void bf8_acc(uint4 r, float* acc) {
    __nv_bfloat162 h0 = *reinterpret_cast<__nv_bfloat162*>(&r.x);
    __nv_bfloat162 h1 = *reinterpret_cast<__nv_bfloat162*>(&r.y);
    __nv_bfloat162 h2 = *reinterpret_cast<__nv_bfloat162*>(&r.z);
    __nv_bfloat162 h3 = *reinterpret_cast<__nv_bfloat162*>(&r.w);
    float2 f0 = __bfloat1622float2(h0), f1 = __bfloat1622float2(h1);
    float2 f2 = __bfloat1622float2(h2), f3 = __bfloat1622float2(h3);
    acc[0] += f0.x; acc[1] += f0.y; acc[2] += f1.x; acc[3] += f1.y;
    acc[4] += f2.x; acc[5] += f2.y; acc[6] += f3.x; acc[7] += f3.y;
}

// ---------------- degree count + edge rank (4 edges/thread, R10 config) ----------------
__global__ void k_count(const int* __restrict__ src, const int* __restrict__ dst, int E) {
    int i = blockIdx.x * blockDim.x + threadIdx.x;
    int base = i * 4;
    int* degO = g_deg;
    int* degI = g_deg + NMAX;
    if (base + 3 < E) {
        int4 s = *(const int4*)(src + base);
        int4 d = *(const int4*)(dst + base);
        atomicAdd(&degO[s.x], 1); atomicAdd(&degO[s.y], 1);
        atomicAdd(&degO[s.z], 1); atomicAdd(&degO[s.w], 1);
        int4 rk;
        rk.x = atomicAdd(&degI[d.x], 1);
        rk.y = atomicAdd(&degI[d.y], 1);
        rk.z = atomicAdd(&degI[d.z], 1);
        rk.w = atomicAdd(&degI[d.w], 1);
        *(int4*)(g_rank + base) = rk;
    } else {
        for (int e = base; e < E; e++) {
            atomicAdd(&g_deg[src[e]], 1);
            g_rank[e] = atomicAdd(&degI[dst[e]], 1);
        }
    }
}

// ---------------- CSR offsets (block scan + atomic base) + degree histogram ----------------
__global__ void k_scan(int n) {
    __shared__ int sh[512];
    __shared__ int sbase;
    int tid = threadIdx.x;
    int i = blockIdx.x * 512 + tid;
    int v = (i < n) ? g_deg[NMAX + i] : 0;
    sh[tid] = v;
    if (i < n) {
        g_si[i] = rsqrtf((float)max(v, 1));
        g_so[i] = rsqrtf((float)max(g_deg[i], 1));
        int b = min(v, 63) * 8 + (i & 7);     // salted degree bucket
        atomicAdd(&g_hist[b], 1);
    }
    __syncthreads();
    #pragma unroll
    for (int off = 1; off < 512; off <<= 1) {
        int t = (tid >= off) ? sh[tid - off] : 0;
        __syncthreads();
        sh[tid] += t;
        __syncthreads();
    }
    if (tid == 511) sbase = atomicAdd(&g_deg[2 * NMAX], sh[511]);
    __syncthreads();
    if (i < n) g_rowptr[i] = sbase + sh[tid] - v;
}

// ---------------- bucket prefix: g_hbase = exclusive scan of g_hist ----------------
__global__ void k_hist() {
    __shared__ int sh[NBKT];
    int tid = threadIdx.x;
    int v = g_hist[tid];
    sh[tid] = v;
    __syncthreads();
    #pragma unroll
    for (int off = 1; off < NBKT; off <<= 1) {
        int t = (tid >= off) ? sh[tid - off] : 0;
        __syncthreads();
        sh[tid] += t;
        __syncthreads();
    }
    g_hbase[tid] = sh[tid] - v;   // exclusive; used as cursor afterward
}

// ---------------- CSR fill (no atomics) + perm fill ----------------
__global__ void k_fillperm(const int* __restrict__ src, const int* __restrict__ dst,
                           int E, int N) {
    int i = blockIdx.x * blockDim.x + threadIdx.x;
    int base = i * 4;
    if (base + 3 < E) {
        int4 s = *(const int4*)(src + base);
        int4 d = *(const int4*)(dst + base);
        int4 rk = *(const int4*)(g_rank + base);
        g_csrc[g_rowptr[d.x] + rk.x] = s.x;
        g_csrc[g_rowptr[d.y] + rk.y] = s.y;
        g_csrc[g_rowptr[d.z] + rk.z] = s.z;
        g_csrc[g_rowptr[d.w] + rk.w] = s.w;
    } else {
        for (int e = base; e < E; e++)
            g_csrc[g_rowptr[dst[e]] + g_rank[e]] = src[e];
    }
    // perm: one thread per node (grid covers E/4 >= N threads)
    if (i < N) {
        int d = g_deg[NMAX + i];
        int b = min(d, 63) * 8 + (i & 7);
        int slot = atomicAdd(&g_hbase[b], 1);
        g_perm[slot] = i;
    }
}

// ---------------- GEMM0: g_bufT = bf16( (X @ W0) * so ) ----------------
__global__ __launch_bounds__(256) void k_gemm0(const float* __restrict__ X,
                                               const float* __restrict__ W0, int N) {
    __shared__ float sX[128][68];
    __shared__ float sW[64][64];
    int tid = threadIdx.x;
    int row0 = blockIdx.x * 128;
    int ty = tid >> 4;
    int tx = tid & 15;

    float acc[8][4] = {};
    #pragma unroll
    for (int kc = 0; kc < 2; kc++) {
        #pragma unroll
        for (int i = 0; i < 8; i++) {
            int flat = i * 256 + tid;
            int r = flat >> 4, q = flat & 15;
            int gr = row0 + r;
            float4 v = make_float4(0.f, 0.f, 0.f, 0.f);
            if (gr < N) v = *(const float4*)(X + (size_t)gr * 128 + kc * 64 + q * 4);
            *(float4*)&sX[r][q * 4] = v;
        }
        #pragma unroll
        for (int i = 0; i < 4; i++) {
            int flat = i * 256 + tid;
            int k = flat >> 4, q = flat & 15;
            *(float4*)&sW[k][q * 4] = *(const float4*)(W0 + (size_t)(kc * 64 + k) * 64 + q * 4);
        }
        __syncthreads();
        #pragma unroll
        for (int k4 = 0; k4 < 16; k4++) {
            float4 w0 = *(float4*)&sW[k4 * 4 + 0][tx * 4];
            float4 w1 = *(float4*)&sW[k4 * 4 + 1][tx * 4];
            float4 w2 = *(float4*)&sW[k4 * 4 + 2][tx * 4];
            float4 w3 = *(float4*)&sW[k4 * 4 + 3][tx * 4];
            #pragma unroll
            for (int i = 0; i < 8; i++) {
                float4 a = *(float4*)&sX[ty * 8 + i][k4 * 4];
                acc[i][0] += a.x * w0.x + a.y * w1.x + a.z * w2.x + a.w * w3.x;
                acc[i][1] += a.x * w0.y + a.y * w1.y + a.z * w2.y + a.w * w3.y;
                acc[i][2] += a.x * w0.z + a.y * w1.z + a.z * w2.z + a.w * w3.z;
                acc[i][3] += a.x * w0.w + a.y * w1.w + a.z * w2.w + a.w * w3.w;
            }
        }
        __syncthreads();
    }
    #pragma unroll
    for (int i = 0; i < 8; i++) {
        int gr = row0 + ty * 8 + i;
        if (gr < N) {
            float s = g_so[gr];
            float4 o = make_float4(acc[i][0] * s, acc[i][1] * s, acc[i][2] * s, acc[i][3] * s);
            *(uint2*)(g_bufT + (size_t)gr * 64 + tx * 4) = f4_to_bf4(o);
        }
    }
}

// ---------------- CSR pull, 64 feats, degree-sorted order, L0 epilogue ----------------
__global__ __launch_bounds__(256) void k_pull64_l0(const float* __restrict__ b0, int N) {
    int idx = blockIdx.x * 32 + (threadIdx.x >> 3);
    if (idx >= N) return;
    int node = g_perm[idx];
    int lane = threadIdx.x & 7;
    int start = g_rowptr[node];
    int cnt = g_deg[NMAX + node];
    float acc[8] = {};
    int j = 0;
    for (; j + 7 < cnt; j += 8) {
        int s0 = __ldg(&g_csrc[start + j]);
        int s1 = __ldg(&g_csrc[start + j + 1]);
        int s2 = __ldg(&g_csrc[start + j + 2]);
        int s3 = __ldg(&g_csrc[start + j + 3]);
        int s4 = __ldg(&g_csrc[start + j + 4]);
        int s5 = __ldg(&g_csrc[start + j + 5]);
        int s6 = __ldg(&g_csrc[start + j + 6]);
        int s7 = __ldg(&g_csrc[start + j + 7]);
        uint4 r0 = *(const uint4*)(g_bufT + (size_t)s0 * 64 + lane * 8);
        uint4 r1 = *(const uint4*)(g_bufT + (size_t)s1 * 64 + lane * 8);
        uint4 r2 = *(const uint4*)(g_bufT + (size_t)s2 * 64 + lane * 8);
        uint4 r3 = *(const uint4*)(g_bufT + (size_t)s3 * 64 + lane * 8);
        uint4 r4 = *(const uint4*)(g_bufT + (size_t)s4 * 64 + lane * 8);
        uint4 r5 = *(const uint4*)(g_bufT + (size_t)s5 * 64 + lane * 8);
        uint4 r6 = *(const uint4*)(g_bufT + (size_t)s6 * 64 + lane * 8);
        uint4 r7 = *(const uint4*)(g_bufT + (size_t)s7 * 64 + lane * 8);
        bf8_acc(r0, acc); bf8_acc(r1, acc); bf8_acc(r2, acc); bf8_acc(r3, acc);
        bf8_acc(r4, acc); bf8_acc(r5, acc); bf8_acc(r6, acc); bf8_acc(r7, acc);
    }
    if (j + 3 < cnt) {
        int s0 = __ldg(&g_csrc[start + j]);
        int s1 = __ldg(&g_csrc[start + j + 1]);
        int s2 = __ldg(&g_csrc[start + j + 2]);
        int s3 = __ldg(&g_csrc[start + j + 3]);
        uint4 r0 = *(const uint4*)(g_bufT + (size_t)s0 * 64 + lane * 8);
        uint4 r1 = *(const uint4*)(g_bufT + (size_t)s1 * 64 + lane * 8);
        uint4 r2 = *(const uint4*)(g_bufT + (size_t)s2 * 64 + lane * 8);
        uint4 r3 = *(const uint4*)(g_bufT + (size_t)s3 * 64 + lane * 8);
        bf8_acc(r0, acc); bf8_acc(r1, acc); bf8_acc(r2, acc); bf8_acc(r3, acc);
        j += 4;
    }
    for (; j < cnt; j++) {
        int s0 = __ldg(&g_csrc[start + j]);
        bf8_acc(*(const uint4*)(g_bufT + (size_t)s0 * 64 + lane * 8), acc);
    }
    float si = g_si[node], so = g_so[node];
    float4 ba = *(const float4*)(b0 + lane * 8);
    float4 bb = *(const float4*)(b0 + lane * 8 + 4);
    float4 o0, o1;
    o0.x = fmaxf(acc[0] * si + ba.x, 0.f) * so;
    o0.y = fmaxf(acc[1] * si + ba.y, 0.f) * so;
    o0.z = fmaxf(acc[2] * si + ba.z, 0.f) * so;
    o0.w = fmaxf(acc[3] * si + ba.w, 0.f) * so;
    o1.x = fmaxf(acc[4] * si + bb.x, 0.f) * so;
    o1.y = fmaxf(acc[5] * si + bb.y, 0.f) * so;
    o1.z = fmaxf(acc[6] * si + bb.z, 0.f) * so;
    o1.w = fmaxf(acc[7] * si + bb.w, 0.f) * so;
    uint2 p0 = f4_to_bf4(o0), p1 = f4_to_bf4(o1);
    *(uint4*)(g_bufA + (size_t)node * 64 + lane * 8) = make_uint4(p0.x, p0.y, p1.x, p1.y);
}

// ---------------- fused L1 pull (degree-sorted) + L1 GEMM + L2 GEMM ----------------
__global__ __launch_bounds__(256) void k_fused_pull12(const float* __restrict__ W1,
                                                      const float* __restrict__ b1,
                                                      const float* __restrict__ W2, int N) {
    __shared__ float sIn[64][68];
    __shared__ float sW1[64][64];
    __shared__ float sW2[64][16];
    __shared__ int   sNode[64];
    int tid = threadIdx.x;
    int row0 = blockIdx.x * 64;

    #pragma unroll
    for (int i = 0; i < 4; i++) {
        int flat = i * 256 + tid;
        int k = flat >> 4, q = flat & 15;
        *(float4*)&sW1[k][q * 4] = *(const float4*)(W1 + (size_t)k * 64 + q * 4);
    }
    {
        int k = tid >> 2, q = tid & 3;
        *(float4*)&sW2[k][q * 4] = *(const float4*)(W2 + (size_t)k * 16 + q * 4);
    }
    if (tid < 64) {
        int gi = row0 + tid;
        sNode[tid] = (gi < N) ? g_perm[gi] : -1;
    }
    __syncthreads();

    // pull phase: 8 lanes/node, 32 nodes per pass, 2 passes
    int lane = tid & 7;
    #pragma unroll
    for (int pass = 0; pass < 2; pass++) {
        int local = pass * 32 + (tid >> 3);
        int node = sNode[local];
        float acc[8] = {};
        if (node >= 0) {
            int start = g_rowptr[node];
            int cnt = g_deg[NMAX + node];
            int j = 0;
            for (; j + 7 < cnt; j += 8) {
                int s0 = __ldg(&g_csrc[start + j]);
                int s1 = __ldg(&g_csrc[start + j + 1]);
                int s2 = __ldg(&g_csrc[start + j + 2]);
                int s3 = __ldg(&g_csrc[start + j + 3]);
                int s4 = __ldg(&g_csrc[start + j + 4]);
                int s5 = __ldg(&g_csrc[start + j + 5]);
                int s6 = __ldg(&g_csrc[start + j + 6]);
                int s7 = __ldg(&g_csrc[start + j + 7]);
                uint4 r0 = *(const uint4*)(g_bufA + (size_t)s0 * 64 + lane * 8);
                uint4 r1 = *(const uint4*)(g_bufA + (size_t)s1 * 64 + lane * 8);
                uint4 r2 = *(const uint4*)(g_bufA + (size_t)s2 * 64 + lane * 8);
                uint4 r3 = *(const uint4*)(g_bufA + (size_t)s3 * 64 + lane * 8);
                uint4 r4 = *(const uint4*)(g_bufA + (size_t)s4 * 64 + lane * 8);
                uint4 r5 = *(const uint4*)(g_bufA + (size_t)s5 * 64 + lane * 8);
                uint4 r6 = *(const uint4*)(g_bufA + (size_t)s6 * 64 + lane * 8);
                uint4 r7 = *(const uint4*)(g_bufA + (size_t)s7 * 64 + lane * 8);
                bf8_acc(r0, acc); bf8_acc(r1, acc); bf8_acc(r2, acc); bf8_acc(r3, acc);
                bf8_acc(r4, acc); bf8_acc(r5, acc); bf8_acc(r6, acc); bf8_acc(r7, acc);
            }
            if (j + 3 < cnt) {
                int s0 = __ldg(&g_csrc[start + j]);
                int s1 = __ldg(&g_csrc[start + j + 1]);
                int s2 = __ldg(&g_csrc[start + j + 2]);
                int s3 = __ldg(&g_csrc[start + j + 3]);
                uint4 r0 = *(const uint4*)(g_bufA + (size_t)s0 * 64 + lane * 8);
                uint4 r1 = *(const uint4*)(g_bufA + (size_t)s1 * 64 + lane * 8);
                uint4 r2 = *(const uint4*)(g_bufA + (size_t)s2 * 64 + lane * 8);
                uint4 r3 = *(const uint4*)(g_bufA + (size_t)s3 * 64 + lane * 8);
                bf8_acc(r0, acc); bf8_acc(r1, acc); bf8_acc(r2, acc); bf8_acc(r3, acc);
                j += 4;
            }
            for (; j < cnt; j++) {
                int s0 = __ldg(&g_csrc[start + j]);
                bf8_acc(*(const uint4*)(g_bufA + (size_t)s0 * 64 + lane * 8), acc);
            }
            float si = g_si[node];
            #pragma unroll
            for (int t = 0; t < 8; t++) acc[t] *= si;
        }
        *(float4*)&sIn[local][lane * 8]     = make_float4(acc[0], acc[1], acc[2], acc[3]);
        *(float4*)&sIn[local][lane * 8 + 4] = make_float4(acc[4], acc[5], acc[6], acc[7]);
    }
    __syncthreads();

    // phase 1: h1 = relu(sIn @ W1 + b1)
    int ty = tid >> 4, tx = tid & 15;
    float acc[4][4] = {};
    #pragma unroll
    for (int k4 = 0; k4 < 16; k4++) {
        float4 w0 = *(float4*)&sW1[k4 * 4 + 0][tx * 4];
        float4 w1 = *(float4*)&sW1[k4 * 4 + 1][tx * 4];
        float4 w2 = *(float4*)&sW1[k4 * 4 + 2][tx * 4];
        float4 w3 = *(float4*)&sW1[k4 * 4 + 3][tx * 4];
        #pragma unroll
        for (int i = 0; i < 4; i++) {
            float4 a = *(float4*)&sIn[ty * 4 + i][k4 * 4];
            acc[i][0] += a.x * w0.x + a.y * w1.x + a.z * w2.x + a.w * w3.x;
            acc[i][1] += a.x * w0.y + a.y * w1.y + a.z * w2.y + a.w * w3.y;
            acc[i][2] += a.x * w0.z + a.y * w1.z + a.z * w2.z + a.w * w3.z;
            acc[i][3] += a.x * w0.w + a.y * w1.w + a.z * w2.w + a.w * w3.w;
        }
    }
    __syncthreads();
    float4 bb = *(const float4*)(b1 + tx * 4);
    #pragma unroll
    for (int i = 0; i < 4; i++) {
        float4 h;
        h.x = fmaxf(acc[i][0] + bb.x, 0.f);
        h.y = fmaxf(acc[i][1] + bb.y, 0.f);
        h.z = fmaxf(acc[i][2] + bb.z, 0.f);
        h.w = fmaxf(acc[i][3] + bb.w, 0.f);
        *(float4*)&sIn[ty * 4 + i][tx * 4] = h;   // sIn now holds h1
    }
    __syncthreads();

    // phase 2: g_bufC[node] = bf16((h1 @ W2) * so)
    int row = tid >> 2;
    int cb = (tid & 3) * 4;
    float4 o = make_float4(0.f, 0.f, 0.f, 0.f);
    #pragma unroll 8
    for (int k = 0; k < 64; k++) {
        float a = sIn[row][k];
        float4 w = *(float4*)&sW2[k][cb];
        o.x += a * w.x; o.y += a * w.y; o.z += a * w.z; o.w += a * w.w;
    }
    int node = sNode[row];
    if (node >= 0) {
        float s = g_so[node];
        o.x *= s; o.y *= s; o.z *= s; o.w *= s;
        *(uint2*)(g_bufC + (size_t)node * 16 + cb) = f4_to_bf4(o);
    }
}

// ---------------- CSR pull, 16 feats, degree-sorted order, final ----------------
__global__ __launch_bounds__(256) void k_pull16(const float* __restrict__ b2,
                                                float* __restrict__ out, int N) {
    int idx = blockIdx.x * 64 + (threadIdx.x >> 2);
    if (idx >= N) return;
    int node = g_perm[idx];
    int lane = threadIdx.x & 3;
    int start = g_rowptr[node];
    int cnt = g_deg[NMAX + node];
    float4 acc = make_float4(0.f, 0.f, 0.f, 0.f);
    int j = 0;
    for (; j + 3 < cnt; j += 4) {
        int s0 = __ldg(&g_csrc[start + j]);
        int s1 = __ldg(&g_csrc[start + j + 1]);
        int s2 = __ldg(&g_csrc[start + j + 2]);
        int s3 = __ldg(&g_csrc[start + j + 3]);
        float4 v0 = bf4_to_f4(*(const uint2*)(g_bufC + (size_t)s0 * 16 + lane * 4));
        float4 v1 = bf4_to_f4(*(const uint2*)(g_bufC + (size_t)s1 * 16 + lane * 4));
        float4 v2 = bf4_to_f4(*(const uint2*)(g_bufC + (size_t)s2 * 16 + lane * 4));
        float4 v3 = bf4_to_f4(*(const uint2*)(g_bufC + (size_t)s3 * 16 + lane * 4));
        acc.x += (v0.x + v1.x) + (v2.x + v3.x);
        acc.y += (v0.y + v1.y) + (v2.y + v3.y);
        acc.z += (v0.z + v1.z) + (v2.z + v3.z);
        acc.w += (v0.w + v1.w) + (v2.w + v3.w);
    }
    for (; j < cnt; j++) {
        int s0 = __ldg(&g_csrc[start + j]);
        float4 v0 = bf4_to_f4(*(const uint2*)(g_bufC + (size_t)s0 * 16 + lane * 4));
        acc.x += v0.x; acc.y += v0.y; acc.z += v0.z; acc.w += v0.w;
    }
    float si = g_si[node];
    float4 b = *(const float4*)(b2 + lane * 4);
    float4 o = make_float4(acc.x * si + b.x, acc.y * si + b.y,
                           acc.z * si + b.z, acc.w * si + b.w);
    *(float4*)(out + (size_t)node * 16 + lane * 4) = o;
}

extern "C" void kernel_launch(void* const* d_in, const int* in_sizes, int n_in,
                              void* d_out, int out_size) {
    const float* X   = (const float*)d_in[0];
    const int*   src = (const int*)d_in[1];
    const int*   dst = (const int*)d_in[2];
    const float* W0  = (const float*)d_in[3];
    const float* b0  = (const float*)d_in[4];
    const float* W1  = (const float*)d_in[5];
    const float* b1  = (const float*)d_in[6];
    const float* W2  = (const float*)d_in[7];
    const float* b2  = (const float*)d_in[8];
    float* out = (float*)d_out;

    int N = in_sizes[0] / 128;
    int E = in_sizes[1];
    int nb = cdiv(N, 512);

    static cudaStream_t s_side = nullptr;
    static cudaEvent_t ev_fork = nullptr, ev_join = nullptr;
    static int res_init = 0;
    if (!res_init) {
        res_init = 1;
        if (cudaStreamCreateWithFlags(&s_side, cudaStreamNonBlocking) != cudaSuccess) s_side = nullptr;
        if (s_side) {
            if (cudaEventCreateWithFlags(&ev_fork, cudaEventDisableTiming) != cudaSuccess ||
                cudaEventCreateWithFlags(&ev_join, cudaEventDisableTiming) != cudaSuccess) {
                s_side = nullptr;
            }
        }
    }

    // memsets: deg array + histogram
    void *pD = nullptr, *pH = nullptr;
    cudaGetSymbolAddress(&pD, g_deg);
    cudaGetSymbolAddress(&pH, g_hist);
    cudaMemsetAsync(pD, 0, (size_t)(2 * NMAX + 1) * sizeof(int), 0);
    cudaMemsetAsync(pH, 0, (size_t)NBKT * sizeof(int), 0);

    k_count<<<cdiv(E, 1024), 256>>>(src, dst, E);
    k_scan<<<nb, 512>>>(N);

    // fork: gemm0 needs g_so (written by k_scan); overlaps hist + fillperm
    if (s_side) {
        cudaEventRecord(ev_fork, 0);
        cudaStreamWaitEvent(s_side, ev_fork, 0);
        k_gemm0<<<cdiv(N, 128), 256, 0, s_side>>>(X, W0, N);
        cudaEventRecord(ev_join, s_side);
    }

    k_hist<<<1, NBKT>>>();
    k_fillperm<<<cdiv(E, 1024), 256>>>(src, dst, E, N);

    if (s_side) cudaStreamWaitEvent(0, ev_join, 0);
    else        k_gemm0<<<cdiv(N, 128), 256>>>(X, W0, N);

    // Layer 0 aggregation + epilogue (degree-sorted node order)
    k_pull64_l0<<<cdiv(N, 32), 256>>>(b0, N);

    // Layer 1 aggregation fused with L1+L2 GEMMs (degree-sorted tiles)
    k_fused_pull12<<<cdiv(N, 64), 256>>>(W1, b1, W2, N);

    // Layer 2 aggregation + final (degree-sorted node order)
    k_pull16<<<cdiv(N, 64), 256>>>(b2, out, N);
}

// round 15
// speedup vs baseline: 1.1403x; 1.1403x over previous
#include <cuda_runtime.h>
#include <cuda_bf16.h>

#define NMAX 100000
#define EMAX 1600000

// Scratch (allocation-free rule: device globals)
__device__ __nv_bfloat16 g_bufT[NMAX * 64];  // bf16 messages (t0, L0)
__device__ __nv_bfloat16 g_bufA[NMAX * 64];  // bf16 messages (h0*so, L1)
__device__ __nv_bfloat16 g_bufC[NMAX * 16];  // t2 (16-feat messages, bf16)
__device__ float g_so[NMAX];                 // rsqrt(max(deg_out,1))
__device__ float g_si[NMAX];                 // rsqrt(max(deg_in,1))
__device__ int   g_deg[2 * NMAX + 1];        // [0,N): degO  [N,2N): degI  [2N]: base allocator
__device__ int   g_rank[EMAX];               // edge rank within dst segment
__device__ int   g_rowptr[NMAX];             // ABSOLUTE CSR segment starts
__device__ int   g_csrc[EMAX];               // CSR: src ids grouped by dst

static inline int cdiv(int a, int b) { return (a + b - 1) / b; }

// ---- bf16 pack/unpack helpers ----
__device__ __forceinline__ float4 bf4_to_f4(uint2 r) {
    __nv_bfloat162 lo = *reinterpret_cast<__nv_bfloat162*>(&r.x);
    __nv_bfloat162 hi = *reinterpret_cast<__nv_bfloat162*>(&r.y);
    float2 a = __bfloat1622float2(lo), b = __bfloat1622float2(hi);
    return make_float4(a.x, a.y, b.x, b.y);
}
__device__ __forceinline__ uint2 f4_to_bf4(float4 v) {
    __nv_bfloat162 lo = __float22bfloat162_rn(make_float2(v.x, v.y));
    __nv_bfloat162 hi = __float22bfloat162_rn(make_float2(v.z, v.w));
    uint2 r;
    r.x = *reinterpret_cast<unsigned*>(&lo);
    r.y = *reinterpret_cast<unsigned*>(&hi);
    return r;
}
__device__ __forceinline__ void bf8_acc(uint4 r, float* acc) {
    __nv_bfloat162 h0 = *reinterpret_cast<__nv_bfloat162*>(&r.x);
    __nv_bfloat162 h1 = *reinterpret_cast<__nv_bfloat162*>(&r.y);
    __nv_bfloat162 h2 = *reinterpret_cast<__nv_bfloat162*>(&r.z);
    __nv_bfloat162 h3 = *reinterpret_cast<__nv_bfloat162*>(&r.w);
    float2 f0 = __bfloat1622float2(h0), f1 = __bfloat1622float2(h1);
    float2 f2 = __bfloat1622float2(h2), f3 = __bfloat1622float2(h3);
    acc[0] += f0.x; acc[1] += f0.y; acc[2] += f1.x; acc[3] += f1.y;
    acc[4] += f2.x; acc[5] += f2.y; acc[6] += f3.x; acc[7] += f3.y;
}

// ---------------- degree count + edge rank (4 edges/thread) ----------------
__global__ void k_count(const int* __restrict__ src, const int* __restrict__ dst, int E) {
    int i = blockIdx.x * blockDim.x + threadIdx.x;
    int base = i * 4;
    int* degO = g_deg;
    int* degI = g_deg + NMAX;
    if (base + 3 < E) {
        int4 s = *(const int4*)(src + base);
        int4 d = *(const int4*)(dst + base);
        atomicAdd(&degO[s.x], 1); atomicAdd(&degO[s.y], 1);
        atomicAdd(&degO[s.z], 1); atomicAdd(&degO[s.w], 1);
        int4 rk;
        rk.x = atomicAdd(&degI[d.x], 1);
        rk.y = atomicAdd(&degI[d.y], 1);
        rk.z = atomicAdd(&degI[d.z], 1);
        rk.w = atomicAdd(&degI[d.w], 1);
        *(int4*)(g_rank + base) = rk;
    } else {
        for (int e = base; e < E; e++) {
            atomicAdd(&degO[src[e]], 1);
            g_rank[e] = atomicAdd(&degI[dst[e]], 1);
        }
    }
}

// ---------------- single-kernel CSR offsets (block-local scan + atomic base) ----------------
// Segment order across blocks is arbitrary but each dst segment is contiguous: valid CSR.
__global__ void k_scan(int n) {
    __shared__ int sh[512];
    __shared__ int sbase;
    int tid = threadIdx.x;
    int i = blockIdx.x * 512 + tid;
    int v = (i < n) ? g_deg[NMAX + i] : 0;
    sh[tid] = v;
    if (i < n) {
        g_si[i] = rsqrtf((float)max(v, 1));
        g_so[i] = rsqrtf((float)max(g_deg[i], 1));
    }
    __syncthreads();
    #pragma unroll
    for (int off = 1; off < 512; off <<= 1) {
        int t = (tid >= off) ? sh[tid - off] : 0;
        __syncthreads();
        sh[tid] += t;
        __syncthreads();
    }
    if (tid == 511) sbase = atomicAdd(&g_deg[2 * NMAX], sh[511]);
    __syncthreads();
    if (i < n) g_rowptr[i] = sbase + sh[tid] - v;
}

// ---------------- CSR fill: NO atomics (rank precomputed) ----------------
__global__ void k_fill(const int* __restrict__ src, const int* __restrict__ dst, int E) {
    int i = blockIdx.x * blockDim.x + threadIdx.x;
    int base = i * 4;
    if (base + 3 < E) {
        int4 s = *(const int4*)(src + base);
        int4 d = *(const int4*)(dst + base);
        int4 rk = *(const int4*)(g_rank + base);
        g_csrc[g_rowptr[d.x] + rk.x] = s.x;
        g_csrc[g_rowptr[d.y] + rk.y] = s.y;
        g_csrc[g_rowptr[d.z] + rk.z] = s.z;
        g_csrc[g_rowptr[d.w] + rk.w] = s.w;
    } else {
        for (int e = base; e < E; e++)
            g_csrc[g_rowptr[dst[e]] + g_rank[e]] = src[e];
    }
}

// ---------------- GEMM0: g_bufT = bf16( (X @ W0) * so ) ----------------
__global__ __launch_bounds__(256) void k_gemm0(const float* __restrict__ X,
                                               const float* __restrict__ W0, int N) {
    __shared__ float sX[128][68];
    __shared__ float sW[64][64];
    int tid = threadIdx.x;
    int row0 = blockIdx.x * 128;
    int ty = tid >> 4;   // rows ty*8..+7
    int tx = tid & 15;   // cols tx*4..+3

    float acc[8][4] = {};
    #pragma unroll
    for (int kc = 0; kc < 2; kc++) {
        #pragma unroll
        for (int i = 0; i < 8; i++) {
            int flat = i * 256 + tid;
            int r = flat >> 4, q = flat & 15;
            int gr = row0 + r;
            float4 v = make_float4(0.f, 0.f, 0.f, 0.f);
            if (gr < N) v = *(const float4*)(X + (size_t)gr * 128 + kc * 64 + q * 4);
            *(float4*)&sX[r][q * 4] = v;
        }
        #pragma unroll
        for (int i = 0; i < 4; i++) {
            int flat = i * 256 + tid;
            int k = flat >> 4, q = flat & 15;
            *(float4*)&sW[k][q * 4] = *(const float4*)(W0 + (size_t)(kc * 64 + k) * 64 + q * 4);
        }
        __syncthreads();
        #pragma unroll
        for (int k4 = 0; k4 < 16; k4++) {
            float4 w0 = *(float4*)&sW[k4 * 4 + 0][tx * 4];
            float4 w1 = *(float4*)&sW[k4 * 4 + 1][tx * 4];
            float4 w2 = *(float4*)&sW[k4 * 4 + 2][tx * 4];
            float4 w3 = *(float4*)&sW[k4 * 4 + 3][tx * 4];
            #pragma unroll
            for (int i = 0; i < 8; i++) {
                float4 a = *(float4*)&sX[ty * 8 + i][k4 * 4];
                acc[i][0] += a.x * w0.x + a.y * w1.x + a.z * w2.x + a.w * w3.x;
                acc[i][1] += a.x * w0.y + a.y * w1.y + a.z * w2.y + a.w * w3.y;
                acc[i][2] += a.x * w0.z + a.y * w1.z + a.z * w2.z + a.w * w3.z;
                acc[i][3] += a.x * w0.w + a.y * w1.w + a.z * w2.w + a.w * w3.w;
            }
        }
        __syncthreads();
    }
    #pragma unroll
    for (int i = 0; i < 8; i++) {
        int gr = row0 + ty * 8 + i;
        if (gr < N) {
            float s = g_so[gr];
            float4 o = make_float4(acc[i][0] * s, acc[i][1] * s, acc[i][2] * s, acc[i][3] * s);
            *(uint2*)(g_bufT + (size_t)gr * 64 + tx * 4) = f4_to_bf4(o);
        }
    }
}

// ---------------- CSR pull, 64 feats (bf16), L0 epilogue ----------------
// 8 lanes/node, 16B loads, 8->4->1 unroll cascade.
__global__ __launch_bounds__(256) void k_pull64_l0(const float* __restrict__ b0, int N) {
    int node = blockIdx.x * 32 + (threadIdx.x >> 3);
    if (node >= N) return;
    int lane = threadIdx.x & 7;
    int start = g_rowptr[node];
    int cnt = g_deg[NMAX + node];
    float acc[8] = {};
    int j = 0;
    for (; j + 7 < cnt; j += 8) {
        int s0 = __ldg(&g_csrc[start + j]);
        int s1 = __ldg(&g_csrc[start + j + 1]);
        int s2 = __ldg(&g_csrc[start + j + 2]);
        int s3 = __ldg(&g_csrc[start + j + 3]);
        int s4 = __ldg(&g_csrc[start + j + 4]);
        int s5 = __ldg(&g_csrc[start + j + 5]);
        int s6 = __ldg(&g_csrc[start + j + 6]);
        int s7 = __ldg(&g_csrc[start + j + 7]);
        uint4 r0 = *(const uint4*)(g_bufT + (size_t)s0 * 64 + lane * 8);
        uint4 r1 = *(const uint4*)(g_bufT + (size_t)s1 * 64 + lane * 8);
        uint4 r2 = *(const uint4*)(g_bufT + (size_t)s2 * 64 + lane * 8);
        uint4 r3 = *(const uint4*)(g_bufT + (size_t)s3 * 64 + lane * 8);
        uint4 r4 = *(const uint4*)(g_bufT + (size_t)s4 * 64 + lane * 8);
        uint4 r5 = *(const uint4*)(g_bufT + (size_t)s5 * 64 + lane * 8);
        uint4 r6 = *(const uint4*)(g_bufT + (size_t)s6 * 64 + lane * 8);
        uint4 r7 = *(const uint4*)(g_bufT + (size_t)s7 * 64 + lane * 8);
        bf8_acc(r0, acc); bf8_acc(r1, acc); bf8_acc(r2, acc); bf8_acc(r3, acc);
        bf8_acc(r4, acc); bf8_acc(r5, acc); bf8_acc(r6, acc); bf8_acc(r7, acc);
    }
    if (j + 3 < cnt) {
        int s0 = __ldg(&g_csrc[start + j]);
        int s1 = __ldg(&g_csrc[start + j + 1]);
        int s2 = __ldg(&g_csrc[start + j + 2]);
        int s3 = __ldg(&g_csrc[start + j + 3]);
        uint4 r0 = *(const uint4*)(g_bufT + (size_t)s0 * 64 + lane * 8);
        uint4 r1 = *(const uint4*)(g_bufT + (size_t)s1 * 64 + lane * 8);
        uint4 r2 = *(const uint4*)(g_bufT + (size_t)s2 * 64 + lane * 8);
        uint4 r3 = *(const uint4*)(g_bufT + (size_t)s3 * 64 + lane * 8);
        bf8_acc(r0, acc); bf8_acc(r1, acc); bf8_acc(r2, acc); bf8_acc(r3, acc);
        j += 4;
    }
    for (; j < cnt; j++) {
        int s0 = __ldg(&g_csrc[start + j]);
        bf8_acc(*(const uint4*)(g_bufT + (size_t)s0 * 64 + lane * 8), acc);
    }
    float si = g_si[node], so = g_so[node];
    float4 ba = *(const float4*)(b0 + lane * 8);
    float4 bb = *(const float4*)(b0 + lane * 8 + 4);
    float4 o0, o1;
    o0.x = fmaxf(acc[0] * si + ba.x, 0.f) * so;
    o0.y = fmaxf(acc[1] * si + ba.y, 0.f) * so;
    o0.z = fmaxf(acc[2] * si + ba.z, 0.f) * so;
    o0.w = fmaxf(acc[3] * si + ba.w, 0.f) * so;
    o1.x = fmaxf(acc[4] * si + bb.x, 0.f) * so;
    o1.y = fmaxf(acc[5] * si + bb.y, 0.f) * so;
    o1.z = fmaxf(acc[6] * si + bb.z, 0.f) * so;
    o1.w = fmaxf(acc[7] * si + bb.w, 0.f) * so;
    uint2 p0 = f4_to_bf4(o0), p1 = f4_to_bf4(o1);
    *(uint4*)(g_bufA + (size_t)node * 64 + lane * 8) = make_uint4(p0.x, p0.y, p1.x, p1.y);
}

// ---------------- fused L1 pull + L1 GEMM + L2 GEMM ----------------
__global__ __launch_bounds__(256) void k_fused_pull12(const float* __restrict__ W1,
                                                      const float* __restrict__ b1,
                                                      const float* __restrict__ W2, int N) {
    __shared__ float sIn[64][68];
    __shared__ float sW1[64][64];
    __shared__ float sW2[64][16];
    int tid = threadIdx.x;
    int row0 = blockIdx.x * 64;

    #pragma unroll
    for (int i = 0; i < 4; i++) {
        int flat = i * 256 + tid;
        int k = flat >> 4, q = flat & 15;
        *(float4*)&sW1[k][q * 4] = *(const float4*)(W1 + (size_t)k * 64 + q * 4);
    }
    {
        int k = tid >> 2, q = tid & 3;
        *(float4*)&sW2[k][q * 4] = *(const float4*)(W2 + (size_t)k * 16 + q * 4);
    }

    // pull phase: 8 lanes/node, 32 nodes per pass, 2 passes, 8->4->1 unroll
    int lane = tid & 7;
    #pragma unroll
    for (int pass = 0; pass < 2; pass++) {
        int local = pass * 32 + (tid >> 3);
        int node = row0 + local;
        float acc[8] = {};
        if (node < N) {
            int start = g_rowptr[node];
            int cnt = g_deg[NMAX + node];
            int j = 0;
            for (; j + 7 < cnt; j += 8) {
                int s0 = __ldg(&g_csrc[start + j]);
                int s1 = __ldg(&g_csrc[start + j + 1]);
                int s2 = __ldg(&g_csrc[start + j + 2]);
                int s3 = __ldg(&g_csrc[start + j + 3]);
                int s4 = __ldg(&g_csrc[start + j + 4]);
                int s5 = __ldg(&g_csrc[start + j + 5]);
                int s6 = __ldg(&g_csrc[start + j + 6]);
                int s7 = __ldg(&g_csrc[start + j + 7]);
                uint4 r0 = *(const uint4*)(g_bufA + (size_t)s0 * 64 + lane * 8);
                uint4 r1 = *(const uint4*)(g_bufA + (size_t)s1 * 64 + lane * 8);
                uint4 r2 = *(const uint4*)(g_bufA + (size_t)s2 * 64 + lane * 8);
                uint4 r3 = *(const uint4*)(g_bufA + (size_t)s3 * 64 + lane * 8);
                uint4 r4 = *(const uint4*)(g_bufA + (size_t)s4 * 64 + lane * 8);
                uint4 r5 = *(const uint4*)(g_bufA + (size_t)s5 * 64 + lane * 8);
                uint4 r6 = *(const uint4*)(g_bufA + (size_t)s6 * 64 + lane * 8);
                uint4 r7 = *(const uint4*)(g_bufA + (size_t)s7 * 64 + lane * 8);
                bf8_acc(r0, acc); bf8_acc(r1, acc); bf8_acc(r2, acc); bf8_acc(r3, acc);
                bf8_acc(r4, acc); bf8_acc(r5, acc); bf8_acc(r6, acc); bf8_acc(r7, acc);
            }
            if (j + 3 < cnt) {
                int s0 = __ldg(&g_csrc[start + j]);
                int s1 = __ldg(&g_csrc[start + j + 1]);
                int s2 = __ldg(&g_csrc[start + j + 2]);
                int s3 = __ldg(&g_csrc[start + j + 3]);
                uint4 r0 = *(const uint4*)(g_bufA + (size_t)s0 * 64 + lane * 8);
                uint4 r1 = *(const uint4*)(g_bufA + (size_t)s1 * 64 + lane * 8);
                uint4 r2 = *(const uint4*)(g_bufA + (size_t)s2 * 64 + lane * 8);
                uint4 r3 = *(const uint4*)(g_bufA + (size_t)s3 * 64 + lane * 8);
                bf8_acc(r0, acc); bf8_acc(r1, acc); bf8_acc(r2, acc); bf8_acc(r3, acc);
                j += 4;
            }
            for (; j < cnt; j++) {
                int s0 = __ldg(&g_csrc[start + j]);
                bf8_acc(*(const uint4*)(g_bufA + (size_t)s0 * 64 + lane * 8), acc);
            }
            float si = g_si[node];
            #pragma unroll
            for (int t = 0; t < 8; t++) acc[t] *= si;
        }
        *(float4*)&sIn[local][lane * 8]     = make_float4(acc[0], acc[1], acc[2], acc[3]);
        *(float4*)&sIn[local][lane * 8 + 4] = make_float4(acc[4], acc[5], acc[6], acc[7]);
    }
    __syncthreads();

    // phase 1: h1 = relu(sIn @ W1 + b1)
    int ty = tid >> 4, tx = tid & 15;
    float acc[4][4] = {};
    #pragma unroll
    for (int k4 = 0; k4 < 16; k4++) {
        float4 w0 = *(float4*)&sW1[k4 * 4 + 0][tx * 4];
        float4 w1 = *(float4*)&sW1[k4 * 4 + 1][tx * 4];
        float4 w2 = *(float4*)&sW1[k4 * 4 + 2][tx * 4];
        float4 w3 = *(float4*)&sW1[k4 * 4 + 3][tx * 4];
        #pragma unroll
        for (int i = 0; i < 4; i++) {
            float4 a = *(float4*)&sIn[ty * 4 + i][k4 * 4];
            acc[i][0] += a.x * w0.x + a.y * w1.x + a.z * w2.x + a.w * w3.x;
            acc[i][1] += a.x * w0.y + a.y * w1.y + a.z * w2.y + a.w * w3.y;
            acc[i][2] += a.x * w0.z + a.y * w1.z + a.z * w2.z + a.w * w3.z;
            acc[i][3] += a.x * w0.w + a.y * w1.w + a.z * w2.w + a.w * w3.w;
        }
    }
    __syncthreads();
    float4 bb = *(const float4*)(b1 + tx * 4);
    #pragma unroll
    for (int i = 0; i < 4; i++) {
        float4 h;
        h.x = fmaxf(acc[i][0] + bb.x, 0.f);
        h.y = fmaxf(acc[i][1] + bb.y, 0.f);
        h.z = fmaxf(acc[i][2] + bb.z, 0.f);
        h.w = fmaxf(acc[i][3] + bb.w, 0.f);
        *(float4*)&sIn[ty * 4 + i][tx * 4] = h;   // sIn now holds h1
    }
    __syncthreads();

    // phase 2: g_bufC = bf16((h1 @ W2) * so)
    int row = tid >> 2;
    int cb = (tid & 3) * 4;
    float4 o = make_float4(0.f, 0.f, 0.f, 0.f);
    #pragma unroll 8
    for (int k = 0; k < 64; k++) {
        float a = sIn[row][k];
        float4 w = *(float4*)&sW2[k][cb];
        o.x += a * w.x; o.y += a * w.y; o.z += a * w.z; o.w += a * w.w;
    }
    int gr = row0 + row;
    if (gr < N) {
        float s = g_so[gr];
        o.x *= s; o.y *= s; o.z *= s; o.w *= s;
        *(uint2*)(g_bufC + (size_t)gr * 16 + cb) = f4_to_bf4(o);
    }
}

// ---------------- CSR pull, 16 feats (bf16), final ----------------
__global__ __launch_bounds__(256) void k_pull16(const float* __restrict__ b2,
                                                float* __restrict__ out, int N) {
    int node = blockIdx.x * 64 + (threadIdx.x >> 2);
    if (node >= N) return;
    int lane = threadIdx.x & 3;
    int start = g_rowptr[node];
    int cnt = g_deg[NMAX + node];
    float4 acc = make_float4(0.f, 0.f, 0.f, 0.f);
    int j = 0;
    for (; j + 3 < cnt; j += 4) {
        int s0 = __ldg(&g_csrc[start + j]);
        int s1 = __ldg(&g_csrc[start + j + 1]);
        int s2 = __ldg(&g_csrc[start + j + 2]);
        int s3 = __ldg(&g_csrc[start + j + 3]);
        float4 v0 = bf4_to_f4(*(const uint2*)(g_bufC + (size_t)s0 * 16 + lane * 4));
        float4 v1 = bf4_to_f4(*(const uint2*)(g_bufC + (size_t)s1 * 16 + lane * 4));
        float4 v2 = bf4_to_f4(*(const uint2*)(g_bufC + (size_t)s2 * 16 + lane * 4));
        float4 v3 = bf4_to_f4(*(const uint2*)(g_bufC + (size_t)s3 * 16 + lane * 4));
        acc.x += (v0.x + v1.x) + (v2.x + v3.x);
        acc.y += (v0.y + v1.y) + (v2.y + v3.y);
        acc.z += (v0.z + v1.z) + (v2.z + v3.z);
        acc.w += (v0.w + v1.w) + (v2.w + v3.w);
    }
    for (; j < cnt; j++) {
        int s0 = __ldg(&g_csrc[start + j]);
        float4 v0 = bf4_to_f4(*(const uint2*)(g_bufC + (size_t)s0 * 16 + lane * 4));
        acc.x += v0.x; acc.y += v0.y; acc.z += v0.z; acc.w += v0.w;
    }
    float si = g_si[node];
    float4 b = *(const float4*)(b2 + lane * 4);
    float4 o = make_float4(acc.x * si + b.x, acc.y * si + b.y,
                           acc.z * si + b.z, acc.w * si + b.w);
    *(float4*)(out + (size_t)node * 16 + lane * 4) = o;
}

extern "C" void kernel_launch(void* const* d_in, const int* in_sizes, int n_in,
                              void* d_out, int out_size) {
    const float* X   = (const float*)d_in[0];
    const int*   src = (const int*)d_in[1];
    const int*   dst = (const int*)d_in[2];
    const float* W0  = (const float*)d_in[3];
    const float* b0  = (const float*)d_in[4];
    const float* W1  = (const float*)d_in[5];
    const float* b1  = (const float*)d_in[6];
    const float* W2  = (const float*)d_in[7];
    const float* b2  = (const float*)d_in[8];
    float* out = (float*)d_out;

    int N = in_sizes[0] / 128;
    int E = in_sizes[1];
    int nb = cdiv(N, 512);

    static cudaStream_t s_side = nullptr;
    static cudaEvent_t ev_fork = nullptr, ev_join = nullptr;
    static int res_init = 0;
    if (!res_init) {
        res_init = 1;
        if (cudaStreamCreateWithFlags(&s_side, cudaStreamNonBlocking) != cudaSuccess) s_side = nullptr;
        if (s_side) {
            if (cudaEventCreateWithFlags(&ev_fork, cudaEventDisableTiming) != cudaSuccess ||
                cudaEventCreateWithFlags(&ev_join, cudaEventDisableTiming) != cudaSuccess) {
                s_side = nullptr;
            }
        }
    }

    // single memset: degO + degI + base allocator
    void* pD = nullptr;
    cudaGetSymbolAddress(&pD, g_deg);
    cudaMemsetAsync(pD, 0, (size_t)(2 * NMAX + 1) * sizeof(int), 0);

    k_count<<<cdiv(E, 1024), 256>>>(src, dst, E);
    k_scan<<<nb, 512>>>(N);

    // fork: gemm0 needs g_so (written by k_scan) — the winning fork position
    if (s_side) {
        cudaEventRecord(ev_fork, 0);
        cudaStreamWaitEvent(s_side, ev_fork, 0);
        k_gemm0<<<cdiv(N, 128), 256, 0, s_side>>>(X, W0, N);
        cudaEventRecord(ev_join, s_side);
    }

    k_fill<<<cdiv(E, 1024), 256>>>(src, dst, E);

    if (s_side) cudaStreamWaitEvent(0, ev_join, 0);
    else        k_gemm0<<<cdiv(N, 128), 256>>>(X, W0, N);

    // Layer 0 aggregation + epilogue
    k_pull64_l0<<<cdiv(N, 32), 256>>>(b0, N);

    // Layer 1 aggregation fused with L1+L2 GEMMs
    k_fused_pull12<<<cdiv(N, 64), 256>>>(W1, b1, W2, N);

    // Layer 2 aggregation + final
    k_pull16<<<cdiv(N, 64), 256>>>(b2, out, N);
}